// round 8
// baseline (speedup 1.0000x reference)
#include <cuda_runtime.h>
#include <cstdint>

#define D_LEN 32768

// ---------------- scratch (static device globals, no allocation) ------------
__device__ __align__(256) float g_a[64 * D_LEN];
__device__ __align__(256) float g_s[64 * D_LEN];
__device__ __align__(256) float g_c[64 * D_LEN];
__device__ double g_part[1280];

__constant__ int c_PI[10] = {0,0,0,0,1,1,1,2,2,3};
__constant__ int c_PJ[10] = {0,1,2,3,1,2,3,2,3,3};

// ---------------- fast fp32 sincos(x), |x| <~ 1000 --------------------------
__device__ __forceinline__ void sincos_fast(float x, float& s_out, float& c_out) {
    const float PIO2_A = 1.5707963705062866f;      // RN(pi/2)
    const float PIO2_B = -4.3711388286737929e-8f;  // pi/2 - PIO2_A
    float q = rintf(x * 0.63661977236758134f);     // 2/pi
    int qi = (int)q;
    float r = fmaf(q, -PIO2_A, x);
    r = fmaf(q, -PIO2_B, r);
    float z = r * r;
    float ps = fmaf(z, fmaf(z, -1.9515295891e-4f, 8.3321608736e-3f), -1.6666654611e-1f);
    float sinr = fmaf(r * z, ps, r);
    float pc = fmaf(z, fmaf(z, 2.443315711809948e-5f, -1.388731625493765e-3f),
                    4.166664568298827e-2f);
    float cosr = fmaf(z * z, pc, fmaf(z, -0.5f, 1.0f));
    float s, c;
    if (qi & 1) { s = cosr; c = -sinr; } else { s = sinr; c = cosr; }
    if (qi & 2) { s = -s; c = -c; }
    s_out = s; c_out = c;
}

// ---------------- pool(4) + sincos(100*m), 4 outputs/thread -----------------
__global__ void pool_kernel(const float* __restrict__ A, const float* __restrict__ B) {
    int idx = blockIdx.x * blockDim.x + threadIdx.x;   // [0, 524288)
    int tensor = idx >> 18;
    int rem = idx & 262143;
    int b  = rem >> 13;                                // 0..31
    int fg = rem & 8191;                               // feat group (4 feats)
    int c   = fg >> 6;
    int ph  = (fg >> 2) & 15;
    int pw0 = (fg & 3) * 4;
    const float* src = tensor ? B : A;
    const float* p = src + ((((b * 128 + c) * 64) + ph * 4) * 64 + pw0 * 4);

    float s0 = 0.f, s1 = 0.f, s2 = 0.f, s3 = 0.f;
    #pragma unroll
    for (int r = 0; r < 4; ++r) {
        const float* q = p + r * 64;
        float4 v0 = __ldcs((const float4*)(q));
        float4 v1 = __ldcs((const float4*)(q + 4));
        float4 v2 = __ldcs((const float4*)(q + 8));
        float4 v3 = __ldcs((const float4*)(q + 12));
        s0 += (v0.x + v0.y) + (v0.z + v0.w);
        s1 += (v1.x + v1.y) + (v1.z + v1.w);
        s2 += (v2.x + v2.y) + (v2.z + v2.w);
        s3 += (v3.x + v3.y) + (v3.z + v3.w);
    }
    float4 m = make_float4(s0 * 0.0625f, s1 * 0.0625f, s2 * 0.0625f, s3 * 0.0625f);
    float4 sv, cv;
    sincos_fast(100.0f * m.x, sv.x, cv.x);
    sincos_fast(100.0f * m.y, sv.y, cv.y);
    sincos_fast(100.0f * m.z, sv.z, cv.z);
    sincos_fast(100.0f * m.w, sv.w, cv.w);

    int row = tensor * 32 + b;
    int off = row * D_LEN + fg * 4;
    *(float4*)(g_a + off) = m;
    *(float4*)(g_s + off) = sv;
    *(float4*)(g_c + off) = cv;
}

// ---------------- pair kernel ------------------------------------------------
__device__ __forceinline__ void cp16(uint32_t dst, const float* src) {
    asm volatile("cp.async.cg.shared.global [%0], [%1], 16;\n" :: "r"(dst), "l"(src));
}
__device__ __forceinline__ float frcp(float x) {
    float r; asm("rcp.approx.ftz.f32 %0, %1;" : "=f"(r) : "f"(x)); return r;
}
__device__ __forceinline__ float wgt(int u, int v, bool diag) {
    if (diag && u >= v) return 0.0f;
    return ((u < 32) == (v < 32)) ? 1.0f : -1.0f;
}

// term = (su*cv - cu*sv) * rcp(d); exact d==0 collisions are skipped
// (their true contribution, T per event, is ~1e-6 relative -- negligible).
#define TERM1(AU,SU,CU,AV,SV,CV,ACC) do {                      \
    float d_ = (AU) - (AV);                                    \
    float r_ = frcp(d_);                                       \
    float t_ = (CU) * (SV);                                    \
    float n_ = fmaf((SU), (CV), -t_);                          \
    if (d_ != 0.0f) (ACC) = fmaf(n_, r_, (ACC));               \
} while (0)

#define TERM4(AU,SU,CU,AV,SV,CV,ACC) do {                      \
    TERM1((AU).x,(SU).x,(CU).x,(AV).x,(SV).x,(CV).x,(ACC));    \
    TERM1((AU).y,(SU).y,(CU).y,(AV).y,(SV).y,(CV).y,(ACC));    \
    TERM1((AU).z,(SU).z,(CU).z,(AV).z,(SV).z,(CV).z,(ACC));    \
    TERM1((AU).w,(SU).w,(CU).w,(AV).w,(SV).w,(CV).w,(ACC));    \
} while (0)

// Padded smem layout: 64 data floats/row + 8 pad => ROWSTR 72 (72 mod 32 = 8).
// Per LDS.128: 8 distinct bank-quads x 4-way broadcast -> conflict-free.
#define ROWSTR 72
#define ARRSTR 1152           /* 16*72 */
#define BUFSTR 6912           /* 6*1152 floats; 27648 B per buffer */
#define KSTAGE 64
#define NSTAGE 4              /* 256 k per block */

__global__ void __launch_bounds__(256, 3) pair_kernel() {
    __shared__ __align__(16) float smem[2 * BUFSTR];
    __shared__ double red[8];
    const int tid = threadIdx.x;
    const int pidx = blockIdx.y;
    const int I = c_PI[pidx], J = c_PJ[pidx];
    const int Ibase = I * 16, Jbase = J * 16;
    const int k0 = blockIdx.x * (KSTAGE * NSTAGE);
    const uint32_t sbase = (uint32_t)__cvta_generic_to_shared(smem);

    const float* srcs[6];
    srcs[0] = g_a + Ibase * D_LEN;
    srcs[1] = g_s + Ibase * D_LEN;
    srcs[2] = g_c + Ibase * D_LEN;
    srcs[3] = g_a + Jbase * D_LEN;
    srcs[4] = g_s + Jbase * D_LEN;
    srcs[5] = g_c + Jbase * D_LEN;

    // loader mapping: 1536 float4 per stage = 6 per thread (one per array)
    const int lrow  = tid >> 4;          // 0..15
    const int lslot = tid & 15;          // 0..15
    const int lsoff = lrow * ROWSTR + lslot * 4;
    const int lgoff = lrow * D_LEN + k0 + lslot * 4;

    #pragma unroll
    for (int j = 0; j < 6; ++j)
        cp16(sbase + 4 * (j * ARRSTR + lsoff), srcs[j] + lgoff);
    asm volatile("cp.async.commit_group;\n");

    // compute mapping: kq 16-way k split, 4x4 register tile over rows
    const int kq = tid >> 4;             // 0..15 -> float4 slot
    const int tu = (tid >> 2) & 3;       // 0..3
    const int tv = tid & 3;              // 0..3
    float acc[4][4];
    #pragma unroll
    for (int i = 0; i < 4; ++i)
        #pragma unroll
        for (int j = 0; j < 4; ++j) acc[i][j] = 0.0f;

    for (int st = 0; st < NSTAGE; ++st) {
        const int buf = st & 1;
        if (st + 1 < NSTAGE) {
            const int nb = buf ^ 1;
            #pragma unroll
            for (int j = 0; j < 6; ++j)
                cp16(sbase + 4 * (nb * BUFSTR + j * ARRSTR + lsoff),
                     srcs[j] + lgoff + (st + 1) * KSTAGE);
            asm volatile("cp.async.commit_group;\n");
            asm volatile("cp.async.wait_group 1;\n");
        } else {
            asm volatile("cp.async.wait_group 0;\n");
        }
        __syncthreads();

        const float* base = smem + buf * BUFSTR + kq * 4;

        // v-columns two at a time: halves live v-registers -> fits occ 3
        #pragma unroll
        for (int jj = 0; jj < 2; ++jj) {
            float4 av[2], sv[2], cv[2];
            #pragma unroll
            for (int j = 0; j < 2; ++j) {
                const int vo = (tv + 4 * (2 * jj + j)) * ROWSTR;
                av[j] = *(const float4*)(base + 3 * ARRSTR + vo);
                sv[j] = *(const float4*)(base + 4 * ARRSTR + vo);
                cv[j] = *(const float4*)(base + 5 * ARRSTR + vo);
            }
            #pragma unroll
            for (int i = 0; i < 4; ++i) {
                const int uo = (tu + 4 * i) * ROWSTR;
                float4 au = *(const float4*)(base + uo);
                float4 su = *(const float4*)(base + ARRSTR + uo);
                float4 cu = *(const float4*)(base + 2 * ARRSTR + uo);
                TERM4(au, su, cu, av[0], sv[0], cv[0], acc[i][2 * jj]);
                TERM4(au, su, cu, av[1], sv[1], cv[1], acc[i][2 * jj + 1]);
            }
        }
        __syncthreads();
    }

    // weights (diagonal tile-pairs count only u<v; cross-tensor sign -1)
    const bool diag = (I == J);
    float tot = 0.0f;
    #pragma unroll
    for (int i = 0; i < 4; ++i) {
        const int u = Ibase + tu + 4 * i;
        #pragma unroll
        for (int j = 0; j < 4; ++j) {
            const int v = Jbase + tv + 4 * j;
            tot += wgt(u, v, diag) * acc[i][j];
        }
    }

    // deterministic block reduction in double
    double td = (double)tot;
    #pragma unroll
    for (int off = 16; off; off >>= 1)
        td += __shfl_down_sync(0xffffffffu, td, off);
    const int warp = tid >> 5, lane = tid & 31;
    if (lane == 0) red[warp] = td;
    __syncthreads();
    if (tid == 0) {
        double ss = 0.0;
        #pragma unroll
        for (int i = 0; i < 8; ++i) ss += red[i];
        g_part[blockIdx.y * 128 + blockIdx.x] = ss;
    }
}

// ---------------- final deterministic reduction ------------------------------
__global__ void final_kernel(float* __restrict__ out) {
    const int tid = threadIdx.x;
    double s = 0.0;
    for (int i = tid; i < 1280; i += 256) s += g_part[i];
    #pragma unroll
    for (int off = 16; off; off >>= 1)
        s += __shfl_down_sync(0xffffffffu, s, off);
    __shared__ double red[8];
    if ((tid & 31) == 0) red[tid >> 5] = s;
    __syncthreads();
    if (tid == 0) {
        double t = 0.0;
        #pragma unroll
        for (int i = 0; i < 8; ++i) t += red[i];
        out[0] = (float)(6.25 + t * (2.0 / 33554432.0));
    }
}

// ---------------- launch ------------------------------------------------------
extern "C" void kernel_launch(void* const* d_in, const int* in_sizes, int n_in,
                              void* d_out, int out_size) {
    (void)in_sizes; (void)n_in; (void)out_size;
    const float* A = (const float*)d_in[0];
    const float* B = (const float*)d_in[1];
    pool_kernel<<<2048, 256>>>(A, B);
    pair_kernel<<<dim3(128, 10), 256>>>();
    final_kernel<<<1, 256>>>((float*)d_out);
}

// round 9
// speedup vs baseline: 1.3098x; 1.3098x over previous
#include <cuda_runtime.h>
#include <cstdint>

#define D_LEN 32768

// ---------------- scratch (static device globals, no allocation) ------------
__device__ __align__(256) float g_a[64 * D_LEN];
__device__ __align__(256) float g_s[64 * D_LEN];
__device__ __align__(256) float g_c[64 * D_LEN];
__device__ double g_part[1280];

__constant__ int c_PI[10] = {0,0,0,0,1,1,1,2,2,3};
__constant__ int c_PJ[10] = {0,1,2,3,1,2,3,2,3,3};

// ---------------- fast fp32 sincos(x), |x| <~ 1000 --------------------------
__device__ __forceinline__ void sincos_fast(float x, float& s_out, float& c_out) {
    const float PIO2_A = 1.5707963705062866f;      // RN(pi/2)
    const float PIO2_B = -4.3711388286737929e-8f;  // pi/2 - PIO2_A
    float q = rintf(x * 0.63661977236758134f);     // 2/pi
    int qi = (int)q;
    float r = fmaf(q, -PIO2_A, x);
    r = fmaf(q, -PIO2_B, r);
    float z = r * r;
    float ps = fmaf(z, fmaf(z, -1.9515295891e-4f, 8.3321608736e-3f), -1.6666654611e-1f);
    float sinr = fmaf(r * z, ps, r);
    float pc = fmaf(z, fmaf(z, 2.443315711809948e-5f, -1.388731625493765e-3f),
                    4.166664568298827e-2f);
    float cosr = fmaf(z * z, pc, fmaf(z, -0.5f, 1.0f));
    float s, c;
    if (qi & 1) { s = cosr; c = -sinr; } else { s = sinr; c = cosr; }
    if (qi & 2) { s = -s; c = -c; }
    s_out = s; c_out = c;
}

// ---------------- pool(4) + sincos(100*m), 4 outputs/thread -----------------
__global__ void pool_kernel(const float* __restrict__ A, const float* __restrict__ B) {
    int idx = blockIdx.x * blockDim.x + threadIdx.x;   // [0, 524288)
    int tensor = idx >> 18;
    int rem = idx & 262143;
    int b  = rem >> 13;                                // 0..31
    int fg = rem & 8191;                               // feat group (4 feats)
    int c   = fg >> 6;
    int ph  = (fg >> 2) & 15;
    int pw0 = (fg & 3) * 4;
    const float* src = tensor ? B : A;
    const float* p = src + ((((b * 128 + c) * 64) + ph * 4) * 64 + pw0 * 4);

    float s0 = 0.f, s1 = 0.f, s2 = 0.f, s3 = 0.f;
    #pragma unroll
    for (int r = 0; r < 4; ++r) {
        const float* q = p + r * 64;
        float4 v0 = __ldcs((const float4*)(q));
        float4 v1 = __ldcs((const float4*)(q + 4));
        float4 v2 = __ldcs((const float4*)(q + 8));
        float4 v3 = __ldcs((const float4*)(q + 12));
        s0 += (v0.x + v0.y) + (v0.z + v0.w);
        s1 += (v1.x + v1.y) + (v1.z + v1.w);
        s2 += (v2.x + v2.y) + (v2.z + v2.w);
        s3 += (v3.x + v3.y) + (v3.z + v3.w);
    }
    float4 m = make_float4(s0 * 0.0625f, s1 * 0.0625f, s2 * 0.0625f, s3 * 0.0625f);
    float4 sv, cv;
    sincos_fast(100.0f * m.x, sv.x, cv.x);
    sincos_fast(100.0f * m.y, sv.y, cv.y);
    sincos_fast(100.0f * m.z, sv.z, cv.z);
    sincos_fast(100.0f * m.w, sv.w, cv.w);

    int row = tensor * 32 + b;
    int off = row * D_LEN + fg * 4;
    *(float4*)(g_a + off) = m;
    *(float4*)(g_s + off) = sv;
    *(float4*)(g_c + off) = cv;
}

// ---------------- pair kernel ------------------------------------------------
__device__ __forceinline__ void cp16(uint32_t dst, const float* src) {
    asm volatile("cp.async.cg.shared.global [%0], [%1], 16;\n" :: "r"(dst), "l"(src));
}
__device__ __forceinline__ float frcp(float x) {
    float r; asm("rcp.approx.ftz.f32 %0, %1;" : "=f"(r) : "f"(x)); return r;
}
__device__ __forceinline__ float wgt(int u, int v, bool diag) {
    if (diag && u >= v) return 0.0f;
    return ((u < 32) == (v < 32)) ? 1.0f : -1.0f;
}

// Pairwise reciprocal: 2 terms share one rcp.
//   w = rcp(d0*d1);  acc += (n0*d1 + n1*d0) * w
// If D==0 the pair is skipped (expected ~4 events total, <=2.4e-5 abs on a
// ~6.25 result -- negligible vs 1e-3 tolerance).
#define TERM2P(AU0,SU0,CU0,AV0,SV0,CV0,AU1,SU1,CU1,AV1,SV1,CV1,ACC) do { \
    float d0_ = (AU0) - (AV0);                                 \
    float d1_ = (AU1) - (AV1);                                 \
    float D_  = d0_ * d1_;                                     \
    float w_  = frcp(D_);                                      \
    float t0_ = (CU0) * (SV0);                                 \
    float n0_ = fmaf((SU0), (CV0), -t0_);                      \
    float t1_ = (CU1) * (SV1);                                 \
    float n1_ = fmaf((SU1), (CV1), -t1_);                      \
    float s_  = n0_ * d1_;                                     \
    s_ = fmaf(n1_, d0_, s_);                                   \
    if (D_ != 0.0f) (ACC) = fmaf(s_, w_, (ACC));               \
} while (0)

#define TERM4(AU,SU,CU,AV,SV,CV,ACC) do {                      \
    TERM2P((AU).x,(SU).x,(CU).x,(AV).x,(SV).x,(CV).x,          \
           (AU).y,(SU).y,(CU).y,(AV).y,(SV).y,(CV).y,(ACC));   \
    TERM2P((AU).z,(SU).z,(CU).z,(AV).z,(SV).z,(CV).z,          \
           (AU).w,(SU).w,(CU).w,(AV).w,(SV).w,(CV).w,(ACC));   \
} while (0)

// Padded smem layout: 64 data floats/row + 8 pad => ROWSTR 72 (72 mod 32 = 8).
// Per LDS.128: 8 distinct bank-quads x 4-way broadcast -> conflict-free.
#define ROWSTR 72
#define ARRSTR 1152           /* 16*72 */
#define BUFSTR 6912           /* 6*1152 floats; 27648 B per buffer */
#define KSTAGE 64
#define NSTAGE 4              /* 256 k per block */

__global__ void __launch_bounds__(256, 2) pair_kernel() {
    __shared__ __align__(16) float smem[2 * BUFSTR];
    __shared__ double red[8];
    const int tid = threadIdx.x;
    const int pidx = blockIdx.y;
    const int I = c_PI[pidx], J = c_PJ[pidx];
    const int Ibase = I * 16, Jbase = J * 16;
    const int k0 = blockIdx.x * (KSTAGE * NSTAGE);
    const uint32_t sbase = (uint32_t)__cvta_generic_to_shared(smem);

    const float* srcs[6];
    srcs[0] = g_a + Ibase * D_LEN;
    srcs[1] = g_s + Ibase * D_LEN;
    srcs[2] = g_c + Ibase * D_LEN;
    srcs[3] = g_a + Jbase * D_LEN;
    srcs[4] = g_s + Jbase * D_LEN;
    srcs[5] = g_c + Jbase * D_LEN;

    // loader mapping: 1536 float4 per stage = 6 per thread (one per array)
    const int lrow  = tid >> 4;          // 0..15
    const int lslot = tid & 15;          // 0..15
    const int lsoff = lrow * ROWSTR + lslot * 4;
    const int lgoff = lrow * D_LEN + k0 + lslot * 4;

    #pragma unroll
    for (int j = 0; j < 6; ++j)
        cp16(sbase + 4 * (j * ARRSTR + lsoff), srcs[j] + lgoff);
    asm volatile("cp.async.commit_group;\n");

    // compute mapping: kq 16-way k split, 4x4 register tile over rows
    const int kq = tid >> 4;             // 0..15 -> float4 slot
    const int tu = (tid >> 2) & 3;       // 0..3
    const int tv = tid & 3;              // 0..3
    float acc[4][4];
    #pragma unroll
    for (int i = 0; i < 4; ++i)
        #pragma unroll
        for (int j = 0; j < 4; ++j) acc[i][j] = 0.0f;

    for (int st = 0; st < NSTAGE; ++st) {
        const int buf = st & 1;
        if (st + 1 < NSTAGE) {
            const int nb = buf ^ 1;
            #pragma unroll
            for (int j = 0; j < 6; ++j)
                cp16(sbase + 4 * (nb * BUFSTR + j * ARRSTR + lsoff),
                     srcs[j] + lgoff + (st + 1) * KSTAGE);
            asm volatile("cp.async.commit_group;\n");
            asm volatile("cp.async.wait_group 1;\n");
        } else {
            asm volatile("cp.async.wait_group 0;\n");
        }
        __syncthreads();

        const float* base = smem + buf * BUFSTR + kq * 4;

        float4 av[4], sv[4], cv[4];
        #pragma unroll
        for (int j = 0; j < 4; ++j) {
            const int vo = (tv + 4 * j) * ROWSTR;
            av[j] = *(const float4*)(base + 3 * ARRSTR + vo);
            sv[j] = *(const float4*)(base + 4 * ARRSTR + vo);
            cv[j] = *(const float4*)(base + 5 * ARRSTR + vo);
        }
        #pragma unroll
        for (int i = 0; i < 4; ++i) {
            const int uo = (tu + 4 * i) * ROWSTR;
            float4 au = *(const float4*)(base + uo);
            float4 su = *(const float4*)(base + ARRSTR + uo);
            float4 cu = *(const float4*)(base + 2 * ARRSTR + uo);
            #pragma unroll
            for (int j = 0; j < 4; ++j)
                TERM4(au, su, cu, av[j], sv[j], cv[j], acc[i][j]);
        }
        __syncthreads();
    }

    // weights (diagonal tile-pairs count only u<v; cross-tensor sign -1)
    const bool diag = (I == J);
    float tot = 0.0f;
    #pragma unroll
    for (int i = 0; i < 4; ++i) {
        const int u = Ibase + tu + 4 * i;
        #pragma unroll
        for (int j = 0; j < 4; ++j) {
            const int v = Jbase + tv + 4 * j;
            tot += wgt(u, v, diag) * acc[i][j];
        }
    }

    // deterministic block reduction in double
    double td = (double)tot;
    #pragma unroll
    for (int off = 16; off; off >>= 1)
        td += __shfl_down_sync(0xffffffffu, td, off);
    const int warp = tid >> 5, lane = tid & 31;
    if (lane == 0) red[warp] = td;
    __syncthreads();
    if (tid == 0) {
        double ss = 0.0;
        #pragma unroll
        for (int i = 0; i < 8; ++i) ss += red[i];
        g_part[blockIdx.y * 128 + blockIdx.x] = ss;
    }
}

// ---------------- final deterministic reduction ------------------------------
__global__ void final_kernel(float* __restrict__ out) {
    const int tid = threadIdx.x;
    double s = 0.0;
    for (int i = tid; i < 1280; i += 256) s += g_part[i];
    #pragma unroll
    for (int off = 16; off; off >>= 1)
        s += __shfl_down_sync(0xffffffffu, s, off);
    __shared__ double red[8];
    if ((tid & 31) == 0) red[tid >> 5] = s;
    __syncthreads();
    if (tid == 0) {
        double t = 0.0;
        #pragma unroll
        for (int i = 0; i < 8; ++i) t += red[i];
        out[0] = (float)(6.25 + t * (2.0 / 33554432.0));
    }
}

// ---------------- launch ------------------------------------------------------
extern "C" void kernel_launch(void* const* d_in, const int* in_sizes, int n_in,
                              void* d_out, int out_size) {
    (void)in_sizes; (void)n_in; (void)out_size;
    const float* A = (const float*)d_in[0];
    const float* B = (const float*)d_in[1];
    pool_kernel<<<2048, 256>>>(A, B);
    pair_kernel<<<dim3(128, 10), 256>>>();
    final_kernel<<<1, 256>>>((float*)d_out);
}